// round 16
// baseline (speedup 1.0000x reference)
#include <cuda_runtime.h>
#include <cuda_fp16.h>
#include <cstdint>
#include <cstddef>

constexpr int B_ = 4, S_ = 2048, H_ = 1024, NH_ = 16, HD_ = 64;
constexpr int M_ = B_ * S_;
constexpr float SCALE_Q = 0.18033688011112042f;  // 0.125 * log2(e)
constexpr float WSC = 32.0f, INV_WSC = 1.0f / 32.0f;

// Scratch
__device__ __half g_xh[(size_t)M_ * H_];
__device__ __half g_wh[4 * (size_t)H_ * H_];
__device__ __half g_q16[(size_t)M_ * H_];
__device__ __half g_k16[(size_t)M_ * H_];
__device__ __half g_v16[(size_t)M_ * H_];
__device__ __half g_ah[(size_t)M_ * H_];

__device__ __forceinline__ uint32_t smem_u32(const void* p) {
    uint32_t a;
    asm("{ .reg .u64 t; cvta.to.shared.u64 t, %1; cvt.u32.u64 %0, t; }"
        : "=r"(a) : "l"(p));
    return a;
}
__device__ __forceinline__ void cp_async16(uint32_t dst, const void* src) {
    asm volatile("cp.async.cg.shared.global [%0], [%1], 16;"
                 :: "r"(dst), "l"(src) : "memory");
}
#define CP_COMMIT() asm volatile("cp.async.commit_group;" ::: "memory")
#define CP_WAIT(n)  asm volatile("cp.async.wait_group %0;" :: "n"(n) : "memory")

__device__ __forceinline__ void ldmatrix_x4(uint32_t* r, uint32_t a) {
    asm volatile("ldmatrix.sync.aligned.m8n8.x4.shared.b16 {%0,%1,%2,%3}, [%4];"
                 : "=r"(r[0]), "=r"(r[1]), "=r"(r[2]), "=r"(r[3]) : "r"(a));
}
__device__ __forceinline__ void ldmatrix_x4_trans(uint32_t* r, uint32_t a) {
    asm volatile("ldmatrix.sync.aligned.m8n8.x4.trans.shared.b16 {%0,%1,%2,%3}, [%4];"
                 : "=r"(r[0]), "=r"(r[1]), "=r"(r[2]), "=r"(r[3]) : "r"(a));
}
__device__ __forceinline__ void mma_f16(float* c, const uint32_t* a,
                                        const uint32_t* b) {
    asm volatile(
        "mma.sync.aligned.m16n8k16.row.col.f32.f16.f16.f32 "
        "{%0,%1,%2,%3}, {%4,%5,%6,%7}, {%8,%9}, {%0,%1,%2,%3};"
        : "+f"(c[0]), "+f"(c[1]), "+f"(c[2]), "+f"(c[3])
        : "r"(a[0]), "r"(a[1]), "r"(a[2]), "r"(a[3]), "r"(b[0]), "r"(b[1]));
}
__device__ __forceinline__ float ex2f(float x) {
    float y; asm("ex2.approx.ftz.f32 %0, %1;" : "=f"(y) : "f"(x)); return y;
}
__device__ __forceinline__ uint32_t f16x2_rn(float h, float l) {
    uint32_t d;
    asm("cvt.rn.f16x2.f32 %0, %1, %2;" : "=r"(d) : "f"(h), "f"(l));
    return d;
}

// ---------------------------------------------------------------------------
// Fused split: one launch. grid.y slots 0-3 = weights (x32, bound n4),
// slot 4 = x (x1, bound n4*8 since M_*H_ == 8 * H_*H_).
// ---------------------------------------------------------------------------
struct SplitArgs { const float* src[5]; __half* dst[5]; };

__global__ __launch_bounds__(256)
void split_all(SplitArgs sa, int n4w)
{
    const int slot = blockIdx.y;
    const int bound = (slot < 4) ? n4w : n4w * 8;   // per-slot element bound
    int i = blockIdx.x * blockDim.x + threadIdx.x;
    if (i >= bound) return;
    const float* src = sa.src[slot];
    __half* dst = sa.dst[slot];
    const float sc = (slot < 4) ? WSC : 1.0f;
    float4 v = reinterpret_cast<const float4*>(src)[i];
    uint2 hu;
    hu.x = f16x2_rn(v.y * sc, v.x * sc);
    hu.y = f16x2_rn(v.w * sc, v.z * sc);
    reinterpret_cast<uint2*>(dst)[i] = hu;
}

// ---------------------------------------------------------------------------
// fp16 single-pass GEMM: C = (A @ (32W)^T)/32 + bias, then *scale.
// ---------------------------------------------------------------------------
constexpr int RPB = 40;
constexpr int TB  = 128 * RPB * 2;
constexpr int O_AH = 0, O_WH = TB;
constexpr int GBUF = 2 * TB;
constexpr int GEMM_SMEM = 2 * GBUF;

struct G3 {
    const float* bias[3];
    __half* out16[3];
    float scale[3];
};

template <int MODE>
__global__ __launch_bounds__(256)
void gemm1(const __half* __restrict__ Ah, const __half* __restrict__ WhB,
           G3 g, float* __restrict__ Cf)
{
    extern __shared__ char smem[];
    const uint32_t sb = smem_u32(smem);
    const int tid = threadIdx.x, wid = tid >> 5, lane = tid & 31;
    const int z = (MODE == 1) ? blockIdx.z : 0;
    const int m0 = blockIdx.y * 128, n0 = blockIdx.x * 128;
    const int wm = (wid & 1) * 64, wn = (wid >> 1) * 32;
    const __half* Wh = WhB + (size_t)z * H_ * H_;

    float acc[4][4][4];
    #pragma unroll
    for (int mi = 0; mi < 4; mi++)
        #pragma unroll
        for (int ni = 0; ni < 4; ni++)
            #pragma unroll
            for (int r = 0; r < 4; r++) acc[mi][ni][r] = 0.f;

    auto issue = [&](int c) {
        const int k0 = c * 32;
        const uint32_t bs = sb + (c & 1) * GBUF;
        #pragma unroll
        for (int t = 0; t < 2; t++) {
            int u = tid + t * 256;
            int row = u >> 2, seg = u & 3;
            uint32_t d = (row * RPB + seg * 8) * 2;
            cp_async16(bs + O_AH + d, Ah + (size_t)(m0 + row) * H_ + k0 + seg * 8);
            cp_async16(bs + O_WH + d, Wh + (size_t)(n0 + row) * H_ + k0 + seg * 8);
        }
        CP_COMMIT();
    };

    issue(0);
    constexpr int NCH = H_ / 32;

    for (int c = 0; c < NCH; c++) {
        if (c + 1 < NCH) { issue(c + 1); CP_WAIT(1); }
        else             { CP_WAIT(0); }
        __syncthreads();
        const uint32_t bs = sb + (c & 1) * GBUF;

        #pragma unroll
        for (int ks = 0; ks < 2; ks++) {
            const int l = lane & 15;
            uint32_t af[4][4], bh[4][2];
            #pragma unroll
            for (int mi = 0; mi < 4; mi++)
                ldmatrix_x4(af[mi], bs + O_AH +
                    ((wm + mi * 16 + l) * RPB + ks * 16 + (lane >> 4) * 8) * 2);
            #pragma unroll
            for (int n2 = 0; n2 < 2; n2++) {
                uint32_t bb[4];
                uint32_t addr = bs + O_WH +
                    ((wn + 8 * (2 * n2 + ((lane >> 4) & 1)) + (lane & 7)) * RPB +
                     ks * 16 + ((lane >> 3) & 1) * 8) * 2;
                ldmatrix_x4(bb, addr);
                bh[2 * n2][0] = bb[0]; bh[2 * n2][1] = bb[1];
                bh[2 * n2 + 1][0] = bb[2]; bh[2 * n2 + 1][1] = bb[3];
            }
            #pragma unroll
            for (int mi = 0; mi < 4; mi++)
                #pragma unroll
                for (int ni = 0; ni < 4; ni++)
                    mma_f16(acc[mi][ni], af[mi], bh[ni]);
        }
        __syncthreads();
    }

    const float scale = g.scale[z];
    const float* bias = g.bias[z];
    const int frow = lane >> 2, fcol = (lane & 3) * 2;
    #pragma unroll
    for (int mi = 0; mi < 4; mi++) {
        #pragma unroll
        for (int ni = 0; ni < 4; ni++) {
            const int n = n0 + wn + ni * 8 + fcol;
            const float b0 = __ldg(&bias[n]);
            const float b1 = __ldg(&bias[n + 1]);
            #pragma unroll
            for (int half = 0; half < 2; half++) {
                const int m = m0 + wm + mi * 16 + frow + half * 8;
                float vx = (acc[mi][ni][half * 2 + 0] * INV_WSC + b0) * scale;
                float vy = (acc[mi][ni][half * 2 + 1] * INV_WSC + b1) * scale;
                if (MODE == 0) {
                    float2 val{vx, vy};
                    *reinterpret_cast<float2*>(&Cf[(size_t)m * H_ + n]) = val;
                } else {
                    const int b = m >> 11, s = m & 2047;
                    const int h = n >> 6, hd = n & 63;
                    size_t idx = (((size_t)(b * NH_ + h)) * S_ + s) * HD_ + hd;
                    reinterpret_cast<uint32_t*>(g.out16[z])[idx >> 1] =
                        f16x2_rn(vy, vx);
                }
            }
        }
    }
}

// ---------------------------------------------------------------------------
// Flash attention, fp16 1-pass QK + 1-pass PV. 3 CTAs/SM (R13 config).
// ---------------------------------------------------------------------------
constexpr int RP = 72, TSZ = 64 * RP * 2;
constexpr int KVBUF = 2 * TSZ;
constexpr int ATTN_SMEM = 2 * KVBUF;    // 36864

__global__ __launch_bounds__(128, 3)
void attn_mma(const __half* __restrict__ q16, const __half* __restrict__ k16,
              const __half* __restrict__ v16, __half* __restrict__ aout)
{
    extern __shared__ char smem[];
    const uint32_t sb = smem_u32(smem);
    const int tid = threadIdx.x, wid = tid >> 5, lane = tid & 31;
    const int qt = 31 - blockIdx.x;
    const int bh = blockIdx.y;
    const int q0 = qt * 64;
    const size_t boff = (size_t)bh * S_ * HD_;
    const int wm = wid * 16;

    auto cp_tile = [&](uint32_t dst, const __half* src) {
        #pragma unroll
        for (int t = 0; t < 4; t++) {
            int u = tid + t * 128, r = u >> 3, ch = u & 7;
            cp_async16(dst + (r * RP + ch * 8) * 2, src + (size_t)r * HD_ + ch * 8);
        }
    };
    const uint32_t qoff = sb + KVBUF;
    cp_tile(qoff, q16 + boff + (size_t)q0 * HD_);
    CP_COMMIT();
    auto issue = [&](int kt) {
        uint32_t kb = sb + (kt & 1) * KVBUF;
        const size_t o = boff + (size_t)kt * 64 * HD_;
        cp_tile(kb, k16 + o);
        cp_tile(kb + TSZ, v16 + o);
        CP_COMMIT();
    };
    issue(0);
    CP_WAIT(1);
    __syncthreads();

    uint32_t qh[4][4];
    #pragma unroll
    for (int ks = 0; ks < 4; ks++) {
        uint32_t a = qoff + ((wm + (lane & 15)) * RP + ks * 16 + (lane >> 4) * 8) * 2;
        ldmatrix_x4(qh[ks], a);
    }
    __syncthreads();

    float o[8][4];
    #pragma unroll
    for (int j = 0; j < 8; j++)
        #pragma unroll
        for (int r = 0; r < 4; r++) o[j][r] = 0.f;
    float m_i[2] = {-1e30f, -1e30f}, l_i[2] = {0.f, 0.f};

    for (int kt = 0; kt <= qt; kt++) {
        if (kt < qt) { issue(kt + 1); CP_WAIT(1); }
        else         { CP_WAIT(0); }
        __syncthreads();
        const uint32_t kb = sb + (kt & 1) * KVBUF;

        float s[8][4];
        #pragma unroll
        for (int j = 0; j < 8; j++)
            #pragma unroll
            for (int r = 0; r < 4; r++) s[j][r] = 0.f;

        #pragma unroll
        for (int ks = 0; ks < 4; ks++) {
            #pragma unroll
            for (int j2 = 0; j2 < 4; j2++) {
                uint32_t bb[4];
                uint32_t ka = kb +
                    ((8 * (2 * j2 + ((lane >> 4) & 1)) + (lane & 7)) * RP +
                     ks * 16 + ((lane >> 3) & 1) * 8) * 2;
                ldmatrix_x4(bb, ka);
                mma_f16(s[2 * j2],     qh[ks], bb);
                mma_f16(s[2 * j2 + 1], qh[ks], bb + 2);
            }
        }

        if (kt == qt) {
            const int r0 = wm + (lane >> 2);
            #pragma unroll
            for (int j = 0; j < 8; j++) {
                const int kc = 8 * j + 2 * (lane & 3);
                if (kc     > r0)     s[j][0] = -1e30f;
                if (kc + 1 > r0)     s[j][1] = -1e30f;
                if (kc     > r0 + 8) s[j][2] = -1e30f;
                if (kc + 1 > r0 + 8) s[j][3] = -1e30f;
            }
        }

        float mx0 = -1e30f, mx1 = -1e30f;
        #pragma unroll
        for (int j = 0; j < 8; j++) {
            mx0 = fmaxf(mx0, fmaxf(s[j][0], s[j][1]));
            mx1 = fmaxf(mx1, fmaxf(s[j][2], s[j][3]));
        }
        mx0 = fmaxf(mx0, __shfl_xor_sync(~0u, mx0, 1));
        mx0 = fmaxf(mx0, __shfl_xor_sync(~0u, mx0, 2));
        mx1 = fmaxf(mx1, __shfl_xor_sync(~0u, mx1, 1));
        mx1 = fmaxf(mx1, __shfl_xor_sync(~0u, mx1, 2));
        const float nm0 = fmaxf(m_i[0], mx0), nm1 = fmaxf(m_i[1], mx1);
        const float c0 = ex2f(m_i[0] - nm0), c1 = ex2f(m_i[1] - nm1);
        m_i[0] = nm0; m_i[1] = nm1;

        float rs0 = 0.f, rs1 = 0.f;
        #pragma unroll
        for (int j = 0; j < 8; j++) {
            s[j][0] = ex2f(s[j][0] - nm0);
            s[j][1] = ex2f(s[j][1] - nm0);
            s[j][2] = ex2f(s[j][2] - nm1);
            s[j][3] = ex2f(s[j][3] - nm1);
            rs0 += s[j][0] + s[j][1];
            rs1 += s[j][2] + s[j][3];
        }
        rs0 += __shfl_xor_sync(~0u, rs0, 1);
        rs0 += __shfl_xor_sync(~0u, rs0, 2);
        rs1 += __shfl_xor_sync(~0u, rs1, 1);
        rs1 += __shfl_xor_sync(~0u, rs1, 2);
        l_i[0] = l_i[0] * c0 + rs0;
        l_i[1] = l_i[1] * c1 + rs1;
        #pragma unroll
        for (int j = 0; j < 8; j++) {
            o[j][0] *= c0; o[j][1] *= c0;
            o[j][2] *= c1; o[j][3] *= c1;
        }

        uint32_t ph[4][4];
        #pragma unroll
        for (int k2 = 0; k2 < 4; k2++) {
            #pragma unroll
            for (int half = 0; half < 2; half++) {
                const int j = 2 * k2 + half;
                ph[k2][half * 2 + 0] = f16x2_rn(s[j][1], s[j][0]);
                ph[k2][half * 2 + 1] = f16x2_rn(s[j][3], s[j][2]);
            }
        }

        const uint32_t vb = kb + TSZ;
        #pragma unroll
        for (int k2 = 0; k2 < 4; k2++) {
            #pragma unroll
            for (int j2 = 0; j2 < 4; j2++) {
                uint32_t vv[4];
                uint32_t va = vb +
                    ((k2 * 16 + (lane & 15)) * RP + 16 * j2 + (lane >> 4) * 8) * 2;
                ldmatrix_x4_trans(vv, va);
                mma_f16(o[2 * j2],     ph[k2], vv);
                mma_f16(o[2 * j2 + 1], ph[k2], vv + 2);
            }
        }
        __syncthreads();
    }

    const float inv0 = 1.f / l_i[0], inv1 = 1.f / l_i[1];
    const int b = bh >> 4, h = bh & 15;
    const int r0 = q0 + wm + (lane >> 2);
    const size_t base0 = ((size_t)(b * S_) + r0) * H_ + h * 64;
    const size_t base1 = base0 + (size_t)8 * H_;
    #pragma unroll
    for (int j = 0; j < 8; j++) {
        const int c = 8 * j + 2 * (lane & 3);
        reinterpret_cast<uint32_t*>(aout)[(base0 + c) >> 1] =
            f16x2_rn(o[j][1] * inv0, o[j][0] * inv0);
        reinterpret_cast<uint32_t*>(aout)[(base1 + c) >> 1] =
            f16x2_rn(o[j][3] * inv1, o[j][2] * inv1);
    }
}

// ---------------------------------------------------------------------------
extern "C" void kernel_launch(void* const* d_in, const int* in_sizes, int n_in,
                              void* d_out, int out_size)
{
    const float* x  = (const float*)d_in[0];
    const float* Wq = (const float*)d_in[1];
    const float* bq = (const float*)d_in[2];
    const float* Wk = (const float*)d_in[3];
    const float* bk = (const float*)d_in[4];
    const float* Wv = (const float*)d_in[5];
    const float* bv = (const float*)d_in[6];
    const float* Wo = (const float*)d_in[7];
    const float* bo = (const float*)d_in[8];
    float* out = (float*)d_out;

    __half *xh, *wh, *ah, *q16, *k16, *v16;
    cudaGetSymbolAddress((void**)&xh, g_xh);
    cudaGetSymbolAddress((void**)&wh, g_wh);
    cudaGetSymbolAddress((void**)&ah, g_ah);
    cudaGetSymbolAddress((void**)&q16, g_q16);
    cudaGetSymbolAddress((void**)&k16, g_k16);
    cudaGetSymbolAddress((void**)&v16, g_v16);

    cudaFuncSetAttribute(gemm1<0>, cudaFuncAttributeMaxDynamicSharedMemorySize, GEMM_SMEM);
    cudaFuncSetAttribute(gemm1<1>, cudaFuncAttributeMaxDynamicSharedMemorySize, GEMM_SMEM);
    cudaFuncSetAttribute(attn_mma, cudaFuncAttributeMaxDynamicSharedMemorySize, ATTN_SMEM);

    const size_t WN = (size_t)H_ * H_;

    // One fused split launch. Grid sized for the largest slot (x = n4w*8);
    // weight slots early-exit via the per-slot bound inside the kernel.
    {
        SplitArgs sa;
        sa.src[0] = Wq; sa.src[1] = Wk; sa.src[2] = Wv; sa.src[3] = Wo;
        sa.src[4] = x;
        sa.dst[0] = wh + 0 * WN; sa.dst[1] = wh + 1 * WN;
        sa.dst[2] = wh + 2 * WN; sa.dst[3] = wh + 3 * WN;
        sa.dst[4] = xh;
        const int n4w = (H_ * H_) / 4;            // 262144
        const int n4x = n4w * 8;                  // 2097152 (= M_*H_/4)
        dim3 wg((n4x + 255) / 256, 5);
        split_all<<<wg, 256>>>(sa, n4w);
    }

    G3 g;
    g.bias[0] = bq;  g.bias[1] = bk;  g.bias[2] = bv;
    g.out16[0] = q16; g.out16[1] = k16; g.out16[2] = v16;
    g.scale[0] = SCALE_Q; g.scale[1] = 1.0f; g.scale[2] = 1.0f;
    dim3 gq(H_ / 128, M_ / 128, 3);
    gemm1<1><<<gq, 256, GEMM_SMEM>>>(xh, wh, g, nullptr);

    dim3 ag(S_ / 64, B_ * NH_);
    attn_mma<<<ag, 128, ATTN_SMEM>>>(q16, k16, v16, ah);

    G3 go;
    go.bias[0] = bo; go.bias[1] = bo; go.bias[2] = bo;
    go.out16[0] = nullptr; go.out16[1] = nullptr; go.out16[2] = nullptr;
    go.scale[0] = 1.0f; go.scale[1] = 1.0f; go.scale[2] = 1.0f;
    dim3 gg(H_ / 128, M_ / 128, 1);
    gemm1<0><<<gg, 256, GEMM_SMEM>>>(ah, wh + 3 * WN, go, out);
}

// round 17
// speedup vs baseline: 1.1901x; 1.1901x over previous
#include <cuda_runtime.h>
#include <cuda_fp16.h>
#include <cstdint>
#include <cstddef>

constexpr int B_ = 4, S_ = 2048, H_ = 1024, NH_ = 16, HD_ = 64;
constexpr int M_ = B_ * S_;
constexpr float SCALE_Q = 0.18033688011112042f;  // 0.125 * log2(e)
constexpr float WSC = 32.0f, INV_WSC = 1.0f / 32.0f;

// Scratch
__device__ __half g_xh[(size_t)M_ * H_];
__device__ __half g_wh[4 * (size_t)H_ * H_];
__device__ __half g_q16[(size_t)M_ * H_];
__device__ __half g_k16[(size_t)M_ * H_];
__device__ __half g_v16[(size_t)M_ * H_];
__device__ __half g_ah[(size_t)M_ * H_];

__device__ __forceinline__ uint32_t smem_u32(const void* p) {
    uint32_t a;
    asm("{ .reg .u64 t; cvta.to.shared.u64 t, %1; cvt.u32.u64 %0, t; }"
        : "=r"(a) : "l"(p));
    return a;
}
__device__ __forceinline__ void cp_async16(uint32_t dst, const void* src) {
    asm volatile("cp.async.cg.shared.global [%0], [%1], 16;"
                 :: "r"(dst), "l"(src) : "memory");
}
#define CP_COMMIT() asm volatile("cp.async.commit_group;" ::: "memory")
#define CP_WAIT(n)  asm volatile("cp.async.wait_group %0;" :: "n"(n) : "memory")

__device__ __forceinline__ void ldmatrix_x4(uint32_t* r, uint32_t a) {
    asm volatile("ldmatrix.sync.aligned.m8n8.x4.shared.b16 {%0,%1,%2,%3}, [%4];"
                 : "=r"(r[0]), "=r"(r[1]), "=r"(r[2]), "=r"(r[3]) : "r"(a));
}
__device__ __forceinline__ void ldmatrix_x4_trans(uint32_t* r, uint32_t a) {
    asm volatile("ldmatrix.sync.aligned.m8n8.x4.trans.shared.b16 {%0,%1,%2,%3}, [%4];"
                 : "=r"(r[0]), "=r"(r[1]), "=r"(r[2]), "=r"(r[3]) : "r"(a));
}
__device__ __forceinline__ void mma_f16(float* c, const uint32_t* a,
                                        const uint32_t* b) {
    asm volatile(
        "mma.sync.aligned.m16n8k16.row.col.f32.f16.f16.f32 "
        "{%0,%1,%2,%3}, {%4,%5,%6,%7}, {%8,%9}, {%0,%1,%2,%3};"
        : "+f"(c[0]), "+f"(c[1]), "+f"(c[2]), "+f"(c[3])
        : "r"(a[0]), "r"(a[1]), "r"(a[2]), "r"(a[3]), "r"(b[0]), "r"(b[1]));
}
__device__ __forceinline__ float ex2f(float x) {
    float y; asm("ex2.approx.ftz.f32 %0, %1;" : "=f"(y) : "f"(x)); return y;
}
__device__ __forceinline__ uint32_t f16x2_rn(float h, float l) {
    uint32_t d;
    asm("cvt.rn.f16x2.f32 %0, %1, %2;" : "=r"(d) : "f"(h), "f"(l));
    return d;
}

// ---------------------------------------------------------------------------
// Splits (separate launches — the fused variant measured +79us, reverted)
// ---------------------------------------------------------------------------
__global__ __launch_bounds__(256)
void split_x(const float* __restrict__ src, __half* __restrict__ h, int n4)
{
    int i = blockIdx.x * blockDim.x + threadIdx.x;
    if (i >= n4) return;
    float4 v = reinterpret_cast<const float4*>(src)[i];
    uint2 hu;
    hu.x = f16x2_rn(v.y, v.x);
    hu.y = f16x2_rn(v.w, v.z);
    reinterpret_cast<uint2*>(h)[i] = hu;
}

struct WSplit { const float* src[4]; };

__global__ __launch_bounds__(256)
void split_w(WSplit ws, __half* __restrict__ hBase, int n4)
{
    const int w = blockIdx.y;
    const float* src = ws.src[w];
    __half* hi = hBase + (size_t)w * H_ * H_;
    int i = blockIdx.x * blockDim.x + threadIdx.x;
    if (i >= n4) return;
    float4 v = reinterpret_cast<const float4*>(src)[i];
    uint2 hu;
    hu.x = f16x2_rn(v.y * WSC, v.x * WSC);
    hu.y = f16x2_rn(v.w * WSC, v.z * WSC);
    reinterpret_cast<uint2*>(hi)[i] = hu;
}

// ---------------------------------------------------------------------------
// fp16 single-pass GEMM: C = (A @ (32W)^T)/32 + bias, then *scale.
// ---------------------------------------------------------------------------
constexpr int RPB = 40;
constexpr int TB  = 128 * RPB * 2;
constexpr int O_AH = 0, O_WH = TB;
constexpr int GBUF = 2 * TB;
constexpr int GEMM_SMEM = 2 * GBUF;

struct G3 {
    const float* bias[3];
    __half* out16[3];
    float scale[3];
};

template <int MODE>
__global__ __launch_bounds__(256)
void gemm1(const __half* __restrict__ Ah, const __half* __restrict__ WhB,
           G3 g, float* __restrict__ Cf)
{
    extern __shared__ char smem[];
    const uint32_t sb = smem_u32(smem);
    const int tid = threadIdx.x, wid = tid >> 5, lane = tid & 31;
    const int z = (MODE == 1) ? blockIdx.z : 0;
    const int m0 = blockIdx.y * 128, n0 = blockIdx.x * 128;
    const int wm = (wid & 1) * 64, wn = (wid >> 1) * 32;
    const __half* Wh = WhB + (size_t)z * H_ * H_;

    float acc[4][4][4];
    #pragma unroll
    for (int mi = 0; mi < 4; mi++)
        #pragma unroll
        for (int ni = 0; ni < 4; ni++)
            #pragma unroll
            for (int r = 0; r < 4; r++) acc[mi][ni][r] = 0.f;

    auto issue = [&](int c) {
        const int k0 = c * 32;
        const uint32_t bs = sb + (c & 1) * GBUF;
        #pragma unroll
        for (int t = 0; t < 2; t++) {
            int u = tid + t * 256;
            int row = u >> 2, seg = u & 3;
            uint32_t d = (row * RPB + seg * 8) * 2;
            cp_async16(bs + O_AH + d, Ah + (size_t)(m0 + row) * H_ + k0 + seg * 8);
            cp_async16(bs + O_WH + d, Wh + (size_t)(n0 + row) * H_ + k0 + seg * 8);
        }
        CP_COMMIT();
    };

    issue(0);
    constexpr int NCH = H_ / 32;

    for (int c = 0; c < NCH; c++) {
        if (c + 1 < NCH) { issue(c + 1); CP_WAIT(1); }
        else             { CP_WAIT(0); }
        __syncthreads();
        const uint32_t bs = sb + (c & 1) * GBUF;

        #pragma unroll
        for (int ks = 0; ks < 2; ks++) {
            const int l = lane & 15;
            uint32_t af[4][4], bh[4][2];
            #pragma unroll
            for (int mi = 0; mi < 4; mi++)
                ldmatrix_x4(af[mi], bs + O_AH +
                    ((wm + mi * 16 + l) * RPB + ks * 16 + (lane >> 4) * 8) * 2);
            #pragma unroll
            for (int n2 = 0; n2 < 2; n2++) {
                uint32_t bb[4];
                uint32_t addr = bs + O_WH +
                    ((wn + 8 * (2 * n2 + ((lane >> 4) & 1)) + (lane & 7)) * RPB +
                     ks * 16 + ((lane >> 3) & 1) * 8) * 2;
                ldmatrix_x4(bb, addr);
                bh[2 * n2][0] = bb[0]; bh[2 * n2][1] = bb[1];
                bh[2 * n2 + 1][0] = bb[2]; bh[2 * n2 + 1][1] = bb[3];
            }
            #pragma unroll
            for (int mi = 0; mi < 4; mi++)
                #pragma unroll
                for (int ni = 0; ni < 4; ni++)
                    mma_f16(acc[mi][ni], af[mi], bh[ni]);
        }
        __syncthreads();
    }

    const float scale = g.scale[z];
    const float* bias = g.bias[z];
    const int frow = lane >> 2, fcol = (lane & 3) * 2;
    #pragma unroll
    for (int mi = 0; mi < 4; mi++) {
        #pragma unroll
        for (int ni = 0; ni < 4; ni++) {
            const int n = n0 + wn + ni * 8 + fcol;
            const float b0 = __ldg(&bias[n]);
            const float b1 = __ldg(&bias[n + 1]);
            #pragma unroll
            for (int half = 0; half < 2; half++) {
                const int m = m0 + wm + mi * 16 + frow + half * 8;
                float vx = (acc[mi][ni][half * 2 + 0] * INV_WSC + b0) * scale;
                float vy = (acc[mi][ni][half * 2 + 1] * INV_WSC + b1) * scale;
                if (MODE == 0) {
                    float2 val{vx, vy};
                    *reinterpret_cast<float2*>(&Cf[(size_t)m * H_ + n]) = val;
                } else {
                    const int b = m >> 11, s = m & 2047;
                    const int h = n >> 6, hd = n & 63;
                    size_t idx = (((size_t)(b * NH_ + h)) * S_ + s) * HD_ + hd;
                    reinterpret_cast<uint32_t*>(g.out16[z])[idx >> 1] =
                        f16x2_rn(vy, vx);
                }
            }
        }
    }
}

// ---------------------------------------------------------------------------
// Flash attention, fp16 1-pass QK + 1-pass PV. 3 CTAs/SM.
// ---------------------------------------------------------------------------
constexpr int RP = 72, TSZ = 64 * RP * 2;
constexpr int KVBUF = 2 * TSZ;
constexpr int ATTN_SMEM = 2 * KVBUF;    // 36864

__global__ __launch_bounds__(128, 3)
void attn_mma(const __half* __restrict__ q16, const __half* __restrict__ k16,
              const __half* __restrict__ v16, __half* __restrict__ aout)
{
    extern __shared__ char smem[];
    const uint32_t sb = smem_u32(smem);
    const int tid = threadIdx.x, wid = tid >> 5, lane = tid & 31;
    const int qt = 31 - blockIdx.x;
    const int bh = blockIdx.y;
    const int q0 = qt * 64;
    const size_t boff = (size_t)bh * S_ * HD_;
    const int wm = wid * 16;

    auto cp_tile = [&](uint32_t dst, const __half* src) {
        #pragma unroll
        for (int t = 0; t < 4; t++) {
            int u = tid + t * 128, r = u >> 3, ch = u & 7;
            cp_async16(dst + (r * RP + ch * 8) * 2, src + (size_t)r * HD_ + ch * 8);
        }
    };
    const uint32_t qoff = sb + KVBUF;
    cp_tile(qoff, q16 + boff + (size_t)q0 * HD_);
    CP_COMMIT();
    auto issue = [&](int kt) {
        uint32_t kb = sb + (kt & 1) * KVBUF;
        const size_t o = boff + (size_t)kt * 64 * HD_;
        cp_tile(kb, k16 + o);
        cp_tile(kb + TSZ, v16 + o);
        CP_COMMIT();
    };
    issue(0);
    CP_WAIT(1);
    __syncthreads();

    uint32_t qh[4][4];
    #pragma unroll
    for (int ks = 0; ks < 4; ks++) {
        uint32_t a = qoff + ((wm + (lane & 15)) * RP + ks * 16 + (lane >> 4) * 8) * 2;
        ldmatrix_x4(qh[ks], a);
    }
    __syncthreads();

    float o[8][4];
    #pragma unroll
    for (int j = 0; j < 8; j++)
        #pragma unroll
        for (int r = 0; r < 4; r++) o[j][r] = 0.f;
    float m_i[2] = {-1e30f, -1e30f}, l_i[2] = {0.f, 0.f};

    for (int kt = 0; kt <= qt; kt++) {
        if (kt < qt) { issue(kt + 1); CP_WAIT(1); }
        else         { CP_WAIT(0); }
        __syncthreads();
        const uint32_t kb = sb + (kt & 1) * KVBUF;

        float s[8][4];
        #pragma unroll
        for (int j = 0; j < 8; j++)
            #pragma unroll
            for (int r = 0; r < 4; r++) s[j][r] = 0.f;

        #pragma unroll
        for (int ks = 0; ks < 4; ks++) {
            #pragma unroll
            for (int j2 = 0; j2 < 4; j2++) {
                uint32_t bb[4];
                uint32_t ka = kb +
                    ((8 * (2 * j2 + ((lane >> 4) & 1)) + (lane & 7)) * RP +
                     ks * 16 + ((lane >> 3) & 1) * 8) * 2;
                ldmatrix_x4(bb, ka);
                mma_f16(s[2 * j2],     qh[ks], bb);
                mma_f16(s[2 * j2 + 1], qh[ks], bb + 2);
            }
        }

        if (kt == qt) {
            const int r0 = wm + (lane >> 2);
            #pragma unroll
            for (int j = 0; j < 8; j++) {
                const int kc = 8 * j + 2 * (lane & 3);
                if (kc     > r0)     s[j][0] = -1e30f;
                if (kc + 1 > r0)     s[j][1] = -1e30f;
                if (kc     > r0 + 8) s[j][2] = -1e30f;
                if (kc + 1 > r0 + 8) s[j][3] = -1e30f;
            }
        }

        float mx0 = -1e30f, mx1 = -1e30f;
        #pragma unroll
        for (int j = 0; j < 8; j++) {
            mx0 = fmaxf(mx0, fmaxf(s[j][0], s[j][1]));
            mx1 = fmaxf(mx1, fmaxf(s[j][2], s[j][3]));
        }
        mx0 = fmaxf(mx0, __shfl_xor_sync(~0u, mx0, 1));
        mx0 = fmaxf(mx0, __shfl_xor_sync(~0u, mx0, 2));
        mx1 = fmaxf(mx1, __shfl_xor_sync(~0u, mx1, 1));
        mx1 = fmaxf(mx1, __shfl_xor_sync(~0u, mx1, 2));
        const float nm0 = fmaxf(m_i[0], mx0), nm1 = fmaxf(m_i[1], mx1);
        const float c0 = ex2f(m_i[0] - nm0), c1 = ex2f(m_i[1] - nm1);
        m_i[0] = nm0; m_i[1] = nm1;

        float rs0 = 0.f, rs1 = 0.f;
        #pragma unroll
        for (int j = 0; j < 8; j++) {
            s[j][0] = ex2f(s[j][0] - nm0);
            s[j][1] = ex2f(s[j][1] - nm0);
            s[j][2] = ex2f(s[j][2] - nm1);
            s[j][3] = ex2f(s[j][3] - nm1);
            rs0 += s[j][0] + s[j][1];
            rs1 += s[j][2] + s[j][3];
        }
        rs0 += __shfl_xor_sync(~0u, rs0, 1);
        rs0 += __shfl_xor_sync(~0u, rs0, 2);
        rs1 += __shfl_xor_sync(~0u, rs1, 1);
        rs1 += __shfl_xor_sync(~0u, rs1, 2);
        l_i[0] = l_i[0] * c0 + rs0;
        l_i[1] = l_i[1] * c1 + rs1;
        #pragma unroll
        for (int j = 0; j < 8; j++) {
            o[j][0] *= c0; o[j][1] *= c0;
            o[j][2] *= c1; o[j][3] *= c1;
        }

        uint32_t ph[4][4];
        #pragma unroll
        for (int k2 = 0; k2 < 4; k2++) {
            #pragma unroll
            for (int half = 0; half < 2; half++) {
                const int j = 2 * k2 + half;
                ph[k2][half * 2 + 0] = f16x2_rn(s[j][1], s[j][0]);
                ph[k2][half * 2 + 1] = f16x2_rn(s[j][3], s[j][2]);
            }
        }

        const uint32_t vb = kb + TSZ;
        #pragma unroll
        for (int k2 = 0; k2 < 4; k2++) {
            #pragma unroll
            for (int j2 = 0; j2 < 4; j2++) {
                uint32_t vv[4];
                uint32_t va = vb +
                    ((k2 * 16 + (lane & 15)) * RP + 16 * j2 + (lane >> 4) * 8) * 2;
                ldmatrix_x4_trans(vv, va);
                mma_f16(o[2 * j2],     ph[k2], vv);
                mma_f16(o[2 * j2 + 1], ph[k2], vv + 2);
            }
        }
        __syncthreads();
    }

    const float inv0 = 1.f / l_i[0], inv1 = 1.f / l_i[1];
    const int b = bh >> 4, h = bh & 15;
    const int r0 = q0 + wm + (lane >> 2);
    const size_t base0 = ((size_t)(b * S_) + r0) * H_ + h * 64;
    const size_t base1 = base0 + (size_t)8 * H_;
    #pragma unroll
    for (int j = 0; j < 8; j++) {
        const int c = 8 * j + 2 * (lane & 3);
        reinterpret_cast<uint32_t*>(aout)[(base0 + c) >> 1] =
            f16x2_rn(o[j][1] * inv0, o[j][0] * inv0);
        reinterpret_cast<uint32_t*>(aout)[(base1 + c) >> 1] =
            f16x2_rn(o[j][3] * inv1, o[j][2] * inv1);
    }
}

// ---------------------------------------------------------------------------
extern "C" void kernel_launch(void* const* d_in, const int* in_sizes, int n_in,
                              void* d_out, int out_size)
{
    const float* x  = (const float*)d_in[0];
    const float* Wq = (const float*)d_in[1];
    const float* bq = (const float*)d_in[2];
    const float* Wk = (const float*)d_in[3];
    const float* bk = (const float*)d_in[4];
    const float* Wv = (const float*)d_in[5];
    const float* bv = (const float*)d_in[6];
    const float* Wo = (const float*)d_in[7];
    const float* bo = (const float*)d_in[8];
    float* out = (float*)d_out;

    __half *xh, *wh, *ah, *q16, *k16, *v16;
    cudaGetSymbolAddress((void**)&xh, g_xh);
    cudaGetSymbolAddress((void**)&wh, g_wh);
    cudaGetSymbolAddress((void**)&ah, g_ah);
    cudaGetSymbolAddress((void**)&q16, g_q16);
    cudaGetSymbolAddress((void**)&k16, g_k16);
    cudaGetSymbolAddress((void**)&v16, g_v16);

    cudaFuncSetAttribute(gemm1<0>, cudaFuncAttributeMaxDynamicSharedMemorySize, GEMM_SMEM);
    cudaFuncSetAttribute(gemm1<1>, cudaFuncAttributeMaxDynamicSharedMemorySize, GEMM_SMEM);
    cudaFuncSetAttribute(attn_mma, cudaFuncAttributeMaxDynamicSharedMemorySize, ATTN_SMEM);

    const size_t WN = (size_t)H_ * H_;

    {
        int n4 = (M_ * H_) / 4;
        split_x<<<(n4 + 255) / 256, 256>>>(x, xh, n4);
        WSplit ws;
        ws.src[0] = Wq; ws.src[1] = Wk; ws.src[2] = Wv; ws.src[3] = Wo;
        int w4 = (H_ * H_) / 4;
        dim3 wg((w4 + 255) / 256, 4);
        split_w<<<wg, 256>>>(ws, wh, w4);
    }

    G3 g;
    g.bias[0] = bq;  g.bias[1] = bk;  g.bias[2] = bv;
    g.out16[0] = q16; g.out16[1] = k16; g.out16[2] = v16;
    g.scale[0] = SCALE_Q; g.scale[1] = 1.0f; g.scale[2] = 1.0f;
    dim3 gq(H_ / 128, M_ / 128, 3);
    gemm1<1><<<gq, 256, GEMM_SMEM>>>(xh, wh, g, nullptr);

    dim3 ag(S_ / 64, B_ * NH_);
    attn_mma<<<ag, 128, ATTN_SMEM>>>(q16, k16, v16, ah);

    G3 go;
    go.bias[0] = bo; go.bias[1] = bo; go.bias[2] = bo;
    go.out16[0] = nullptr; go.out16[1] = nullptr; go.out16[2] = nullptr;
    go.scale[0] = 1.0f; go.scale[1] = 1.0f; go.scale[2] = 1.0f;
    dim3 gg(H_ / 128, M_ / 128, 1);
    gemm1<0><<<gg, 256, GEMM_SMEM>>>(ah, wh + 3 * WN, go, out);
}